// round 9
// baseline (speedup 1.0000x reference)
#include <cuda_runtime.h>

// RITS-I, GB300 sm_103a. grid=128 CTAs x 256 threads, 2 batches/CTA packed f32x2.
// 2 __syncthreads per step. Gate partials stay in registers across the barrier;
// pointwise resolved by intra-warp shuffles (i,f,g,o rows co-located per warp).
//
// Thread map (w=warp 0..7, l=lane): pair q=l>>1, half hf=l&1.
//   gate row  = 32*(q>>2) + 4*w + (q&3)   (pair splits the 64-wide dot halves)
//   W_reg     : feature f=tid>>2, eighth e=tid&3 (quad computes one x_h)
//   gamma     : row 4w+(l&3), eighth e8=l>>2  (8-way split, no duplication;
//               reduced over lane bits 2,3,4; b_decay seeded at e8==0)
//   pointwise : lanes l<8: h-row j=4w+(l>>1), batch l&1

#define NB 256
#define NT 2048
#define NI 64
#define NH 32
#define NC 2
#define TPB 256
#define FULL 0xffffffffu

typedef unsigned long long ull;

__device__ __forceinline__ ull pack2(float x, float y) {
    ull r; asm("mov.b64 %0, {%1, %2};" : "=l"(r) : "f"(x), "f"(y)); return r;
}
__device__ __forceinline__ void unpack2(ull v, float& x, float& y) {
    asm("mov.b64 {%0, %1}, %2;" : "=f"(x), "=f"(y) : "l"(v));
}
__device__ __forceinline__ ull ffma2(ull a, ull b, ull c) {
    ull d; asm("fma.rn.f32x2 %0, %1, %2, %3;" : "=l"(d) : "l"(a), "l"(b), "l"(c));
    return d;
}
__device__ __forceinline__ ull fadd2(ull a, ull b) {
    ull d; asm("add.rn.f32x2 %0, %1, %2;" : "=l"(d) : "l"(a), "l"(b)); return d;
}

__device__ __forceinline__ float sigmoid_f(float x) {
    float e = __expf(-x);
    return __fdividef(1.0f, 1.0f + e);
}
__device__ __forceinline__ float tanh_f(float x) {
    float ax = fabsf(x);
    float e  = __expf(-2.0f * ax);
    float r  = __fdividef(1.0f - e, 1.0f + e);
    return copysignf(r, x);
}

__global__ void __launch_bounds__(TPB, 1)
rits_kernel(const float* __restrict__ values,
            const float* __restrict__ masks,
            const float* __restrict__ deltas,
            const float* __restrict__ W_decay, const float* __restrict__ b_decay,
            const float* __restrict__ W_reg,   const float* __restrict__ b_reg,
            const float* __restrict__ W_ih,    const float* __restrict__ b_ih,
            const float* __restrict__ W_hh,    const float* __restrict__ b_hh,
            const float* __restrict__ W_out,   const float* __restrict__ b_out,
            float* __restrict__ out)
{
    // packed layout: feature f -> [2f]=batch0, [2f+1]=batch1
    __shared__ __align__(16) float x_s[2][2 * NI];
    __shared__ __align__(16) float m_s[2][2 * NI];
    __shared__ __align__(16) float d_s[2][2 * NI];
    __shared__ __align__(16) float xc_s[2 * NI];
    __shared__ __align__(16) float h_s[2 * NH];

    const int tid = threadIdx.x;
    const int w = tid >> 5, l = tid & 31;
    const int q = l >> 1, hf = l & 1;
    const int g_row = ((q >> 2) << 5) + (w << 2) + (q & 3);
    const int f_reg = tid >> 2, e_reg = tid & 3;
    const int row_g = (w << 2) + (l & 3);   // gamma row (8-way split)
    const int e8    = l >> 2;               // gamma eighth

    const size_t base0 = (size_t)(2 * blockIdx.x) * NT * NI;
    const size_t base1 = base0 + (size_t)NT * NI;

    // ---- weights: gate row halves packed-duplicated; W_reg/W_decay scalar ----
    ull wx[32], wm[32], wh[16];
    float wr[8], wd[8];
    {
        const float* pw = W_ih + (size_t)g_row * (2 * NI) + hf * 32;
        #pragma unroll
        for (int i = 0; i < 32; i++) wx[i] = pack2(pw[i], pw[i]);
        #pragma unroll
        for (int i = 0; i < 32; i++) wm[i] = pack2(pw[64 + i], pw[64 + i]);
        const float* ph = W_hh + (size_t)g_row * NH + hf * 16;
        #pragma unroll
        for (int i = 0; i < 16; i++) wh[i] = pack2(ph[i], ph[i]);
        const float* pr = W_reg + (size_t)f_reg * NH + e_reg * 8;
        #pragma unroll
        for (int i = 0; i < 8; i++) wr[i] = pr[i];
        const float* pd_ = W_decay + (size_t)row_g * NI + e8 * 8;
        #pragma unroll
        for (int i = 0; i < 8; i++) wd[i] = pd_[i];
    }
    const float bs    = (hf == 0) ? (b_ih[g_row] + b_hh[g_row]) : 0.0f;
    const ull   bsum2 = pack2(bs, bs);
    const float brg   = b_reg[f_reg];
    const float bdsd  = (e8 == 0) ? b_decay[row_g] : 0.0f;   // gamma seed

    float c_reg = 0.0f;   // lanes l<8: cell state for (row 4w+(l>>1), batch l&1)

    // ---- stage step 0; prefetch step 1 ----
    float px = 0.f, pm = 0.f, pd = 0.f;
    if (tid < 2 * NH) h_s[tid] = 0.0f;
    if (tid < 128) {
        const int f = tid >> 1;
        const size_t bb = (tid & 1) ? base1 : base0;
        x_s[0][tid] = values[bb + f];
        m_s[0][tid] = masks [bb + f];
        px = values[bb + NI + f];
        pm = masks [bb + NI + f];
    } else {
        const int s = tid - 128, f = s >> 1;
        const size_t bb = (s & 1) ? base1 : base0;
        d_s[0][s] = deltas[bb + f];
        pd = deltas[bb + NI + f];
    }
    __syncthreads();

    float* __restrict__ imp_out = out + (size_t)NB * NC;

    for (int t = 0; t < NT; t++) {
        const int par = t & 1, nb = par ^ 1;

        // ============ Phase A ============
        // gate partial: bsum + (m-half).m + Whh.h   (h_s is pre-decayed)
        ull a0 = bsum2, a1 = 0ull;
        {
            const ulonglong2* mp = (const ulonglong2*)(m_s[par] + (hf << 6));
            #pragma unroll
            for (int k = 0; k < 16; k++) {
                ulonglong2 v = mp[k];
                a0 = ffma2(wm[2 * k],     v.x, a0);
                a1 = ffma2(wm[2 * k + 1], v.y, a1);
            }
            const ulonglong2* hp = (const ulonglong2*)(h_s + (hf << 5));
            #pragma unroll
            for (int k = 0; k < 8; k++) {
                ulonglong2 v = hp[k];
                a0 = ffma2(wh[2 * k],     v.x, a0);
                a1 = ffma2(wh[2 * k + 1], v.y, a1);
            }
        }
        const ull gpart = fadd2(a0, a1);   // lives across the barrier

        // x_h (scalar x2 batches), quad-reduced; then x_c + imputation store
        {
            float s0 = 0.f, s1 = 0.f;
            const float4* hq = (const float4*)(h_s + (e_reg << 4));
            #pragma unroll
            for (int k = 0; k < 4; k++) {
                float4 v = hq[k];
                s0 = fmaf(wr[2 * k],     v.x, s0);
                s1 = fmaf(wr[2 * k],     v.y, s1);
                s0 = fmaf(wr[2 * k + 1], v.z, s0);
                s1 = fmaf(wr[2 * k + 1], v.w, s1);
            }
            s0 += __shfl_xor_sync(FULL, s0, 1);
            s1 += __shfl_xor_sync(FULL, s1, 1);
            s0 += __shfl_xor_sync(FULL, s0, 2);
            s1 += __shfl_xor_sync(FULL, s1, 2);
            if ((tid & 3) == 0) {
                const float xh0 = s0 + brg, xh1 = s1 + brg;
                const float m0 = m_s[par][2 * f_reg], m1 = m_s[par][2 * f_reg + 1];
                const float x0 = x_s[par][2 * f_reg], x1 = x_s[par][2 * f_reg + 1];
                const float xc0 = m0 * x0 + (1.0f - m0) * xh0;
                const float xc1 = m1 * x1 + (1.0f - m1) * xh1;
                xc_s[2 * f_reg]     = xc0;
                xc_s[2 * f_reg + 1] = xc1;
                imp_out[base0 + (size_t)t * NI + f_reg] = xc0;
                imp_out[base1 + (size_t)t * NI + f_reg] = xc1;
            }
        }

        // stage step t+1 into alt buffers; prefetch step t+2
        if (tid < 128) {
            x_s[nb][tid] = px; m_s[nb][tid] = pm;
            if (t + 2 < NT) {
                const int f = tid >> 1;
                const size_t bb = (tid & 1) ? base1 : base0;
                const size_t o = bb + (size_t)(t + 2) * NI + f;
                px = values[o]; pm = masks[o];
            }
        } else {
            const int s = tid - 128;
            d_s[nb][s] = pd;
            if (t + 2 < NT) {
                const int f = s >> 1;
                const size_t bb = (s & 1) ? base1 : base0;
                pd = deltas[bb + (size_t)(t + 2) * NI + f];
            }
        }
        __syncthreads();

        // ============ Phase B ============
        // finish gates: add x-half onto register partial; pair-combine by shfl
        ull b0 = gpart, b1 = 0ull;
        {
            const ulonglong2* xp = (const ulonglong2*)(xc_s + (hf << 6));
            #pragma unroll
            for (int k = 0; k < 16; k++) {
                ulonglong2 v = xp[k];
                b0 = ffma2(wx[2 * k],     v.x, b0);
                b1 = ffma2(wx[2 * k + 1], v.y, b1);
            }
        }
        ull g = fadd2(b0, b1);
        g = fadd2(g, __shfl_xor_sync(FULL, g, 1));   // full gate on both lanes

        // gamma_{t+1} (scalar x2), 8-way split, bias seeded at e8==0
        float ga0 = bdsd, ga1 = bdsd;
        {
            const float4* dp = (const float4*)(d_s[nb] + (e8 << 4));
            #pragma unroll
            for (int k = 0; k < 4; k++) {
                float4 v = dp[k];
                ga0 = fmaf(wd[2 * k],     v.x, ga0);
                ga1 = fmaf(wd[2 * k],     v.y, ga1);
                ga0 = fmaf(wd[2 * k + 1], v.z, ga0);
                ga1 = fmaf(wd[2 * k + 1], v.w, ga1);
            }
            ga0 += __shfl_xor_sync(FULL, ga0, 4);
            ga1 += __shfl_xor_sync(FULL, ga1, 4);
            ga0 += __shfl_xor_sync(FULL, ga0, 8);
            ga1 += __shfl_xor_sync(FULL, ga1, 8);
            ga0 += __shfl_xor_sync(FULL, ga0, 16);
            ga1 += __shfl_xor_sync(FULL, ga1, 16);
        }
        // lane l<8 pulls row j=4w+(l>>1) totals from lane l>>1 (row 4w+((l>>1)&3))
        const float gam0 = __shfl_sync(FULL, ga0, l >> 1);
        const float gam1 = __shfl_sync(FULL, ga1, l >> 1);

        // gather f,g,o gate rows (i is own) — warp-wide shuffles
        const ull gF = __shfl_sync(FULL, g, (l + 8)  & 31);
        const ull gG = __shfl_sync(FULL, g, (l + 16) & 31);
        const ull gO = __shfl_sync(FULL, g, (l + 24) & 31);

        if (l < 8) {
            const int bsel = l & 1;
            const int j = (w << 2) + (l >> 1);
            float t0, t1, gi, gf, gg, go;
            unpack2(g,  t0, t1); gi = bsel ? t1 : t0;
            unpack2(gF, t0, t1); gf = bsel ? t1 : t0;
            unpack2(gG, t0, t1); gg = bsel ? t1 : t0;
            unpack2(gO, t0, t1); go = bsel ? t1 : t0;
            const float graw  = bsel ? gam1 : gam0;   // already includes b_decay
            const float gamma = (t + 1 < NT)
                              ? __expf(-fmaxf(graw, 0.0f)) : 1.0f;
            const float ig = sigmoid_f(gi);
            const float fg = sigmoid_f(gf);
            const float tg = tanh_f(gg);
            const float og = sigmoid_f(go);
            const float cn = fg * c_reg + ig * tg;
            c_reg = cn;
            h_s[2 * j + bsel] = og * tanh_f(cn) * gamma;   // pre-decayed
        }
        __syncthreads();
    }

    // ---- output head: 4 scalars (2 batches x 2 classes) ----
    if (tid < 4) {
        const int cc = tid & 1, bsel = tid >> 1;
        float s = b_out[cc];
        #pragma unroll
        for (int jj = 0; jj < NH; jj++)
            s += W_out[cc * NH + jj] * h_s[2 * jj + bsel];
        out[(size_t)(2 * blockIdx.x + bsel) * NC + cc] = s;
    }
}

extern "C" void kernel_launch(void* const* d_in, const int* in_sizes, int n_in,
                              void* d_out, int out_size)
{
    (void)in_sizes; (void)n_in; (void)out_size;
    const float* values  = (const float*)d_in[0];
    const float* masks   = (const float*)d_in[1];
    const float* deltas  = (const float*)d_in[2];
    const float* W_decay = (const float*)d_in[3];
    const float* b_decay = (const float*)d_in[4];
    const float* W_reg   = (const float*)d_in[5];
    const float* b_reg   = (const float*)d_in[6];
    const float* W_ih    = (const float*)d_in[7];
    const float* b_ih    = (const float*)d_in[8];
    const float* W_hh    = (const float*)d_in[9];
    const float* b_hh    = (const float*)d_in[10];
    const float* W_out   = (const float*)d_in[11];
    const float* b_out   = (const float*)d_in[12];
    float* out = (float*)d_out;

    rits_kernel<<<NB / 2, TPB>>>(values, masks, deltas,
                                 W_decay, b_decay, W_reg, b_reg,
                                 W_ih, b_ih, W_hh, b_hh,
                                 W_out, b_out, out);
}

// round 15
// speedup vs baseline: 1.0000x; 1.0000x over previous
#include <cuda_runtime.h>

// RITS-I, GB300 sm_103a. grid=128 CTAs x 256 threads, 2 batches/CTA packed f32x2.
// 2 __syncthreads per step. Gate partials stay in registers across the barrier;
// pointwise resolved by intra-warp shuffles (i,f,g,o rows co-located per warp).
//
// Thread map (w=warp 0..7, l=lane): pair q=l>>1, half hf=l&1.
//   gate row  = 32*(q>>2) + 4*w + (q&3)   (pair splits the 64-wide dot halves)
//   W_reg     : feature f=tid>>2, eighth e=tid&3 (quad computes one x_h)
//   gamma     : row 4w+(l&3), eighth e8=l>>2  (8-way split, no duplication;
//               reduced over lane bits 2,3,4; b_decay seeded at e8==0)
//   pointwise : lanes l<8: h-row j=4w+(l>>1), batch l&1

#define NB 256
#define NT 2048
#define NI 64
#define NH 32
#define NC 2
#define TPB 256
#define FULL 0xffffffffu

typedef unsigned long long ull;

__device__ __forceinline__ ull pack2(float x, float y) {
    ull r; asm("mov.b64 %0, {%1, %2};" : "=l"(r) : "f"(x), "f"(y)); return r;
}
__device__ __forceinline__ void unpack2(ull v, float& x, float& y) {
    asm("mov.b64 {%0, %1}, %2;" : "=f"(x), "=f"(y) : "l"(v));
}
__device__ __forceinline__ ull ffma2(ull a, ull b, ull c) {
    ull d; asm("fma.rn.f32x2 %0, %1, %2, %3;" : "=l"(d) : "l"(a), "l"(b), "l"(c));
    return d;
}
__device__ __forceinline__ ull fadd2(ull a, ull b) {
    ull d; asm("add.rn.f32x2 %0, %1, %2;" : "=l"(d) : "l"(a), "l"(b)); return d;
}

__device__ __forceinline__ float sigmoid_f(float x) {
    float e = __expf(-x);
    return __fdividef(1.0f, 1.0f + e);
}
__device__ __forceinline__ float tanh_f(float x) {
    float ax = fabsf(x);
    float e  = __expf(-2.0f * ax);
    float r  = __fdividef(1.0f - e, 1.0f + e);
    return copysignf(r, x);
}

__global__ void __launch_bounds__(TPB, 1)
rits_kernel(const float* __restrict__ values,
            const float* __restrict__ masks,
            const float* __restrict__ deltas,
            const float* __restrict__ W_decay, const float* __restrict__ b_decay,
            const float* __restrict__ W_reg,   const float* __restrict__ b_reg,
            const float* __restrict__ W_ih,    const float* __restrict__ b_ih,
            const float* __restrict__ W_hh,    const float* __restrict__ b_hh,
            const float* __restrict__ W_out,   const float* __restrict__ b_out,
            float* __restrict__ out)
{
    // packed layout: feature f -> [2f]=batch0, [2f+1]=batch1
    __shared__ __align__(16) float x_s[2][2 * NI];
    __shared__ __align__(16) float m_s[2][2 * NI];
    __shared__ __align__(16) float d_s[2][2 * NI];
    __shared__ __align__(16) float xc_s[2 * NI];
    __shared__ __align__(16) float h_s[2 * NH];

    const int tid = threadIdx.x;
    const int w = tid >> 5, l = tid & 31;
    const int q = l >> 1, hf = l & 1;
    const int g_row = ((q >> 2) << 5) + (w << 2) + (q & 3);
    const int f_reg = tid >> 2, e_reg = tid & 3;
    const int row_g = (w << 2) + (l & 3);   // gamma row (8-way split)
    const int e8    = l >> 2;               // gamma eighth

    const size_t base0 = (size_t)(2 * blockIdx.x) * NT * NI;
    const size_t base1 = base0 + (size_t)NT * NI;

    // ---- weights: gate row halves packed-duplicated; W_reg/W_decay scalar ----
    ull wx[32], wm[32], wh[16];
    float wr[8], wd[8];
    {
        const float* pw = W_ih + (size_t)g_row * (2 * NI) + hf * 32;
        #pragma unroll
        for (int i = 0; i < 32; i++) wx[i] = pack2(pw[i], pw[i]);
        #pragma unroll
        for (int i = 0; i < 32; i++) wm[i] = pack2(pw[64 + i], pw[64 + i]);
        const float* ph = W_hh + (size_t)g_row * NH + hf * 16;
        #pragma unroll
        for (int i = 0; i < 16; i++) wh[i] = pack2(ph[i], ph[i]);
        const float* pr = W_reg + (size_t)f_reg * NH + e_reg * 8;
        #pragma unroll
        for (int i = 0; i < 8; i++) wr[i] = pr[i];
        const float* pd_ = W_decay + (size_t)row_g * NI + e8 * 8;
        #pragma unroll
        for (int i = 0; i < 8; i++) wd[i] = pd_[i];
    }
    const float bs    = (hf == 0) ? (b_ih[g_row] + b_hh[g_row]) : 0.0f;
    const ull   bsum2 = pack2(bs, bs);
    const float brg   = b_reg[f_reg];
    const float bdsd  = (e8 == 0) ? b_decay[row_g] : 0.0f;   // gamma seed

    float c_reg = 0.0f;   // lanes l<8: cell state for (row 4w+(l>>1), batch l&1)

    // ---- stage step 0; prefetch step 1 ----
    float px = 0.f, pm = 0.f, pd = 0.f;
    if (tid < 2 * NH) h_s[tid] = 0.0f;
    if (tid < 128) {
        const int f = tid >> 1;
        const size_t bb = (tid & 1) ? base1 : base0;
        x_s[0][tid] = values[bb + f];
        m_s[0][tid] = masks [bb + f];
        px = values[bb + NI + f];
        pm = masks [bb + NI + f];
    } else {
        const int s = tid - 128, f = s >> 1;
        const size_t bb = (s & 1) ? base1 : base0;
        d_s[0][s] = deltas[bb + f];
        pd = deltas[bb + NI + f];
    }
    __syncthreads();

    float* __restrict__ imp_out = out + (size_t)NB * NC;

    for (int t = 0; t < NT; t++) {
        const int par = t & 1, nb = par ^ 1;

        // ============ Phase A ============
        // gate partial: bsum + (m-half).m + Whh.h   (h_s is pre-decayed)
        ull a0 = bsum2, a1 = 0ull;
        {
            const ulonglong2* mp = (const ulonglong2*)(m_s[par] + (hf << 6));
            #pragma unroll
            for (int k = 0; k < 16; k++) {
                ulonglong2 v = mp[k];
                a0 = ffma2(wm[2 * k],     v.x, a0);
                a1 = ffma2(wm[2 * k + 1], v.y, a1);
            }
            const ulonglong2* hp = (const ulonglong2*)(h_s + (hf << 5));
            #pragma unroll
            for (int k = 0; k < 8; k++) {
                ulonglong2 v = hp[k];
                a0 = ffma2(wh[2 * k],     v.x, a0);
                a1 = ffma2(wh[2 * k + 1], v.y, a1);
            }
        }
        const ull gpart = fadd2(a0, a1);   // lives across the barrier

        // x_h (scalar x2 batches), quad-reduced; then x_c + imputation store
        {
            float s0 = 0.f, s1 = 0.f;
            const float4* hq = (const float4*)(h_s + (e_reg << 4));
            #pragma unroll
            for (int k = 0; k < 4; k++) {
                float4 v = hq[k];
                s0 = fmaf(wr[2 * k],     v.x, s0);
                s1 = fmaf(wr[2 * k],     v.y, s1);
                s0 = fmaf(wr[2 * k + 1], v.z, s0);
                s1 = fmaf(wr[2 * k + 1], v.w, s1);
            }
            s0 += __shfl_xor_sync(FULL, s0, 1);
            s1 += __shfl_xor_sync(FULL, s1, 1);
            s0 += __shfl_xor_sync(FULL, s0, 2);
            s1 += __shfl_xor_sync(FULL, s1, 2);
            if ((tid & 3) == 0) {
                const float xh0 = s0 + brg, xh1 = s1 + brg;
                const float m0 = m_s[par][2 * f_reg], m1 = m_s[par][2 * f_reg + 1];
                const float x0 = x_s[par][2 * f_reg], x1 = x_s[par][2 * f_reg + 1];
                const float xc0 = m0 * x0 + (1.0f - m0) * xh0;
                const float xc1 = m1 * x1 + (1.0f - m1) * xh1;
                xc_s[2 * f_reg]     = xc0;
                xc_s[2 * f_reg + 1] = xc1;
                imp_out[base0 + (size_t)t * NI + f_reg] = xc0;
                imp_out[base1 + (size_t)t * NI + f_reg] = xc1;
            }
        }

        // stage step t+1 into alt buffers; prefetch step t+2
        if (tid < 128) {
            x_s[nb][tid] = px; m_s[nb][tid] = pm;
            if (t + 2 < NT) {
                const int f = tid >> 1;
                const size_t bb = (tid & 1) ? base1 : base0;
                const size_t o = bb + (size_t)(t + 2) * NI + f;
                px = values[o]; pm = masks[o];
            }
        } else {
            const int s = tid - 128;
            d_s[nb][s] = pd;
            if (t + 2 < NT) {
                const int f = s >> 1;
                const size_t bb = (s & 1) ? base1 : base0;
                pd = deltas[bb + (size_t)(t + 2) * NI + f];
            }
        }
        __syncthreads();

        // ============ Phase B ============
        // finish gates: add x-half onto register partial; pair-combine by shfl
        ull b0 = gpart, b1 = 0ull;
        {
            const ulonglong2* xp = (const ulonglong2*)(xc_s + (hf << 6));
            #pragma unroll
            for (int k = 0; k < 16; k++) {
                ulonglong2 v = xp[k];
                b0 = ffma2(wx[2 * k],     v.x, b0);
                b1 = ffma2(wx[2 * k + 1], v.y, b1);
            }
        }
        ull g = fadd2(b0, b1);
        g = fadd2(g, __shfl_xor_sync(FULL, g, 1));   // full gate on both lanes

        // gamma_{t+1} (scalar x2), 8-way split, bias seeded at e8==0
        float ga0 = bdsd, ga1 = bdsd;
        {
            const float4* dp = (const float4*)(d_s[nb] + (e8 << 4));
            #pragma unroll
            for (int k = 0; k < 4; k++) {
                float4 v = dp[k];
                ga0 = fmaf(wd[2 * k],     v.x, ga0);
                ga1 = fmaf(wd[2 * k],     v.y, ga1);
                ga0 = fmaf(wd[2 * k + 1], v.z, ga0);
                ga1 = fmaf(wd[2 * k + 1], v.w, ga1);
            }
            ga0 += __shfl_xor_sync(FULL, ga0, 4);
            ga1 += __shfl_xor_sync(FULL, ga1, 4);
            ga0 += __shfl_xor_sync(FULL, ga0, 8);
            ga1 += __shfl_xor_sync(FULL, ga1, 8);
            ga0 += __shfl_xor_sync(FULL, ga0, 16);
            ga1 += __shfl_xor_sync(FULL, ga1, 16);
        }
        // lane l<8 pulls row j=4w+(l>>1) totals from lane l>>1 (row 4w+((l>>1)&3))
        const float gam0 = __shfl_sync(FULL, ga0, l >> 1);
        const float gam1 = __shfl_sync(FULL, ga1, l >> 1);

        // gather f,g,o gate rows (i is own) — warp-wide shuffles
        const ull gF = __shfl_sync(FULL, g, (l + 8)  & 31);
        const ull gG = __shfl_sync(FULL, g, (l + 16) & 31);
        const ull gO = __shfl_sync(FULL, g, (l + 24) & 31);

        if (l < 8) {
            const int bsel = l & 1;
            const int j = (w << 2) + (l >> 1);
            float t0, t1, gi, gf, gg, go;
            unpack2(g,  t0, t1); gi = bsel ? t1 : t0;
            unpack2(gF, t0, t1); gf = bsel ? t1 : t0;
            unpack2(gG, t0, t1); gg = bsel ? t1 : t0;
            unpack2(gO, t0, t1); go = bsel ? t1 : t0;
            const float graw  = bsel ? gam1 : gam0;   // already includes b_decay
            const float gamma = (t + 1 < NT)
                              ? __expf(-fmaxf(graw, 0.0f)) : 1.0f;
            const float ig = sigmoid_f(gi);
            const float fg = sigmoid_f(gf);
            const float tg = tanh_f(gg);
            const float og = sigmoid_f(go);
            const float cn = fg * c_reg + ig * tg;
            c_reg = cn;
            h_s[2 * j + bsel] = og * tanh_f(cn) * gamma;   // pre-decayed
        }
        __syncthreads();
    }

    // ---- output head: 4 scalars (2 batches x 2 classes) ----
    if (tid < 4) {
        const int cc = tid & 1, bsel = tid >> 1;
        float s = b_out[cc];
        #pragma unroll
        for (int jj = 0; jj < NH; jj++)
            s += W_out[cc * NH + jj] * h_s[2 * jj + bsel];
        out[(size_t)(2 * blockIdx.x + bsel) * NC + cc] = s;
    }
}

extern "C" void kernel_launch(void* const* d_in, const int* in_sizes, int n_in,
                              void* d_out, int out_size)
{
    (void)in_sizes; (void)n_in; (void)out_size;
    const float* values  = (const float*)d_in[0];
    const float* masks   = (const float*)d_in[1];
    const float* deltas  = (const float*)d_in[2];
    const float* W_decay = (const float*)d_in[3];
    const float* b_decay = (const float*)d_in[4];
    const float* W_reg   = (const float*)d_in[5];
    const float* b_reg   = (const float*)d_in[6];
    const float* W_ih    = (const float*)d_in[7];
    const float* b_ih    = (const float*)d_in[8];
    const float* W_hh    = (const float*)d_in[9];
    const float* b_hh    = (const float*)d_in[10];
    const float* W_out   = (const float*)d_in[11];
    const float* b_out   = (const float*)d_in[12];
    float* out = (float*)d_out;

    rits_kernel<<<NB / 2, TPB>>>(values, masks, deltas,
                                 W_decay, b_decay, W_reg, b_reg,
                                 W_ih, b_ih, W_hh, b_hh,
                                 W_out, b_out, out);
}

// round 17
// speedup vs baseline: 1.2031x; 1.2031x over previous
#include <cuda_runtime.h>

// RITS-I, GB300 sm_103a. grid=128 CTAs x 256 threads, 2 batches/CTA.
// MIO-minimizing layout: f32x2 packs GATE-ROW PAIRS (i,f) and (g,o), one batch
// per thread, so each activation LDS feeds 4 gate rows; (a,a) operands built
// with ALU mov.b64 packs instead of extra shared-memory traffic.
//
// Thread map: tid = b*128 + j*4 + q   (j = h-row 0..31, q = quarter, b = batch)
//   gate dot : quarter q covers input cols [32q,32q+32) of [x_c | m] (q0,q1 = x;
//              q2,q3 = m); W_hh split 8 cols per quarter; reduce = shfl xor 1,2.
//   x_h      : q0/q1 threads, features (2j,2j+1) packed, h half per q.
//   gamma    : q2/q3 threads, col-pair-packed ffma2 dot over d(t+1).
//   pointwise: q0 thread owns (j,b) — i,f,g,o arrive co-located, no gathers.
// 2 __syncthreads per step; m-dot of t+1 overlaps the pointwise tail.

#define NB 256
#define NT 2048
#define NI 64
#define NH 32
#define NC 2
#define TPB 256
#define FULL 0xffffffffu

typedef unsigned long long ull;

__device__ __forceinline__ ull pack2(float x, float y) {
    ull r; asm("mov.b64 %0, {%1, %2};" : "=l"(r) : "f"(x), "f"(y)); return r;
}
__device__ __forceinline__ ull dup2(float v) {
    ull r; asm("mov.b64 %0, {%1, %1};" : "=l"(r) : "f"(v)); return r;
}
__device__ __forceinline__ void unpack2(ull v, float& x, float& y) {
    asm("mov.b64 {%0, %1}, %2;" : "=f"(x), "=f"(y) : "l"(v));
}
__device__ __forceinline__ ull ffma2(ull a, ull b, ull c) {
    ull d; asm("fma.rn.f32x2 %0, %1, %2, %3;" : "=l"(d) : "l"(a), "l"(b), "l"(c));
    return d;
}
__device__ __forceinline__ ull fadd2(ull a, ull b) {
    ull d; asm("add.rn.f32x2 %0, %1, %2;" : "=l"(d) : "l"(a), "l"(b)); return d;
}

__device__ __forceinline__ float sigmoid_f(float x) {
    float e = __expf(-x);
    return __fdividef(1.0f, 1.0f + e);
}
__device__ __forceinline__ float tanh_f(float x) {
    float ax = fabsf(x);
    float e  = __expf(-2.0f * ax);
    float r  = __fdividef(1.0f - e, 1.0f + e);
    return copysignf(r, x);
}

// one float4 of activations -> 4 gate rows x 4 cols (8 ffma2, 4 ALU packs)
__device__ __forceinline__ void gate_fma4(const ull* wi, const ull* wg,
                                          float4 v, ull& aif, ull& ago) {
    ull d0 = dup2(v.x), d1 = dup2(v.y), d2 = dup2(v.z), d3 = dup2(v.w);
    aif = ffma2(wi[0], d0, aif); ago = ffma2(wg[0], d0, ago);
    aif = ffma2(wi[1], d1, aif); ago = ffma2(wg[1], d1, ago);
    aif = ffma2(wi[2], d2, aif); ago = ffma2(wg[2], d2, ago);
    aif = ffma2(wi[3], d3, aif); ago = ffma2(wg[3], d3, ago);
}

__global__ void __launch_bounds__(TPB, 1)
rits_kernel(const float* __restrict__ values,
            const float* __restrict__ masks,
            const float* __restrict__ deltas,
            const float* __restrict__ W_decay, const float* __restrict__ b_decay,
            const float* __restrict__ W_reg,   const float* __restrict__ b_reg,
            const float* __restrict__ W_ih,    const float* __restrict__ b_ih,
            const float* __restrict__ W_hh,    const float* __restrict__ b_hh,
            const float* __restrict__ W_out,   const float* __restrict__ b_out,
            float* __restrict__ out)
{
    __shared__ __align__(16) float x_s[2][2][NI];   // [buf][batch][feat]
    __shared__ __align__(16) float m_s[2][2][NI];
    __shared__ __align__(16) float d_s[2][2][NI];
    __shared__ __align__(16) float xc_s[2][NI];     // [batch][feat]
    __shared__ __align__(16) float h_s[2][NH];      // [batch][j]  (pre-decayed)

    const int tid = threadIdx.x;
    const int q   = tid & 3;
    const int j   = (tid >> 2) & 31;
    const int b   = tid >> 7;
    const int l   = tid & 31;

    const size_t base0 = (size_t)(2 * blockIdx.x) * NT * NI;
    const size_t base1 = base0 + (size_t)NT * NI;
    const size_t baseb = b ? base1 : base0;

    // ---- weights: gate-row-pair packed; quarter q = input cols [32q,32q+32) ----
    ull wif[32], wgo[32], whif[8], whgo[8], role[16];
    {
        const float* Wi = W_ih + (size_t)j            * (2 * NI) + 32 * q;
        const float* Wf = W_ih + (size_t)(NH + j)     * (2 * NI) + 32 * q;
        const float* Wg = W_ih + (size_t)(2 * NH + j) * (2 * NI) + 32 * q;
        const float* Wo = W_ih + (size_t)(3 * NH + j) * (2 * NI) + 32 * q;
        #pragma unroll
        for (int k = 0; k < 32; k++) {
            wif[k] = pack2(Wi[k], Wf[k]);
            wgo[k] = pack2(Wg[k], Wo[k]);
        }
        const float* Hi = W_hh + (size_t)j            * NH + 8 * q;
        const float* Hf = W_hh + (size_t)(NH + j)     * NH + 8 * q;
        const float* Hg = W_hh + (size_t)(2 * NH + j) * NH + 8 * q;
        const float* Ho = W_hh + (size_t)(3 * NH + j) * NH + 8 * q;
        #pragma unroll
        for (int k = 0; k < 8; k++) {
            whif[k] = pack2(Hi[k], Hf[k]);
            whgo[k] = pack2(Hg[k], Ho[k]);
        }
        if (q < 2) {   // W_reg: features (2j,2j+1) packed, h cols [16q,16q+16)
            const float* R0 = W_reg + (size_t)(2 * j)     * NH + 16 * q;
            const float* R1 = W_reg + (size_t)(2 * j + 1) * NH + 16 * q;
            #pragma unroll
            for (int k = 0; k < 16; k++) role[k] = pack2(R0[k], R1[k]);
        } else {       // W_decay: row j, col-pairs over d cols [32(q-2), +32)
            const float* D = W_decay + (size_t)j * NI + 32 * (q - 2);
            #pragma unroll
            for (int k = 0; k < 16; k++) role[k] = pack2(D[2 * k], D[2 * k + 1]);
        }
    }
    ull bias_if = 0, bias_go = 0, brg2 = 0;
    float bd = 0.0f;
    if (q == 2) {
        bias_if = pack2(b_ih[j] + b_hh[j],             b_ih[NH + j] + b_hh[NH + j]);
        bias_go = pack2(b_ih[2*NH + j] + b_hh[2*NH + j], b_ih[3*NH + j] + b_hh[3*NH + j]);
        bd = b_decay[j];
    }
    if (q == 0) brg2 = pack2(b_reg[2 * j], b_reg[2 * j + 1]);

    float c_reg = 0.0f;   // valid on q==0

    // ---- stage step 0; prefetch step 1 ----
    float px = 0.f, pm = 0.f, pd = 0.f;
    if (tid < 2 * NH) ((float*)h_s)[tid] = 0.0f;
    if (tid < 128) {
        const int f = tid >> 1;
        const size_t bb = (tid & 1) ? base1 : base0;
        x_s[0][tid & 1][f] = values[bb + f];
        m_s[0][tid & 1][f] = masks [bb + f];
        px = values[bb + NI + f];
        pm = masks [bb + NI + f];
    } else {
        const int s = tid - 128, f = s >> 1;
        const size_t bb = (s & 1) ? base1 : base0;
        d_s[0][s & 1][f] = deltas[bb + f];
        pd = deltas[bb + NI + f];
    }
    __syncthreads();

    // ---- pre-loop m-dot for t = 0 (q2/q3) ----
    ull macc_if = bias_if, macc_go = bias_go;
    if (q >= 2) {
        const float4* mp = (const float4*)&m_s[0][b][32 * (q - 2)];
        #pragma unroll
        for (int k = 0; k < 8; k++)
            gate_fma4(&wif[4 * k], &wgo[4 * k], mp[k], macc_if, macc_go);
    }

    float* __restrict__ imp_out = out + (size_t)NB * NC;

    for (int t = 0; t < NT; t++) {
        const int par = t & 1, nb = par ^ 1;

        // ============ Phase A ============
        // gate partial = m-part(+bias) + W_hh.h  (h_s is pre-decayed)
        ull gif = macc_if, ggo = macc_go;
        {
            const float4* hp = (const float4*)&h_s[b][8 * q];
            gate_fma4(&whif[0], &whgo[0], hp[0], gif, ggo);
            gate_fma4(&whif[4], &whgo[4], hp[1], gif, ggo);
        }

        // x_h on q0/q1 (features 2j,2j+1 packed; h half per q)
        ull xacc = brg2;
        if (q < 2) {
            const float4* hp = (const float4*)&h_s[b][16 * q];
            #pragma unroll
            for (int k = 0; k < 4; k++) {
                float4 v = hp[k];
                xacc = ffma2(role[4 * k + 0], dup2(v.x), xacc);
                xacc = ffma2(role[4 * k + 1], dup2(v.y), xacc);
                xacc = ffma2(role[4 * k + 2], dup2(v.z), xacc);
                xacc = ffma2(role[4 * k + 3], dup2(v.w), xacc);
            }
        }
        xacc = fadd2(xacc, __shfl_xor_sync(FULL, xacc, 1));   // q0+q1 (uniform)
        if (q == 0) {
            float xh0, xh1; unpack2(xacc, xh0, xh1);
            const float2 mv = *(const float2*)&m_s[par][b][2 * j];
            const float2 xv = *(const float2*)&x_s[par][b][2 * j];
            const float xc0 = mv.x * xv.x + (1.0f - mv.x) * xh0;
            const float xc1 = mv.y * xv.y + (1.0f - mv.y) * xh1;
            *(float2*)&xc_s[b][2 * j] = make_float2(xc0, xc1);
            *(float2*)&imp_out[baseb + (size_t)t * NI + 2 * j] = make_float2(xc0, xc1);
        }

        // stage step t+1 into alt buffers; prefetch step t+2
        if (tid < 128) {
            x_s[nb][tid & 1][tid >> 1] = px;
            m_s[nb][tid & 1][tid >> 1] = pm;
            if (t + 2 < NT) {
                const size_t bb = (tid & 1) ? base1 : base0;
                const size_t o = bb + (size_t)(t + 2) * NI + (tid >> 1);
                px = values[o]; pm = masks[o];
            }
        } else {
            const int s = tid - 128;
            d_s[nb][s & 1][s >> 1] = pd;
            if (t + 2 < NT) {
                const size_t bb = (s & 1) ? base1 : base0;
                pd = deltas[bb + (size_t)(t + 2) * NI + (s >> 1)];
            }
        }
        __syncthreads();

        // ============ Phase B ============
        float graw = bd;
        if (q < 2) {
            // x-quarter of the gate dot
            const float4* xp = (const float4*)&xc_s[b][32 * q];
            #pragma unroll
            for (int k = 0; k < 8; k++)
                gate_fma4(&wif[4 * k], &wgo[4 * k], xp[k], gif, ggo);
        } else {
            // gamma(t+1) half-dot, col-pair packed (no ALU packs needed)
            ull ga = 0ull;
            const ulonglong2* dp = (const ulonglong2*)&d_s[nb][b][32 * (q - 2)];
            #pragma unroll
            for (int k = 0; k < 8; k++) {
                ulonglong2 v = dp[k];
                ga = ffma2(role[2 * k],     v.x, ga);
                ga = ffma2(role[2 * k + 1], v.y, ga);
            }
            float g0, g1; unpack2(ga, g0, g1);
            graw += g0 + g1;
        }
        graw += __shfl_xor_sync(FULL, graw, 1);               // q2+q3 (uniform)
        const float gamma_raw = __shfl_sync(FULL, graw, l | 2);  // q2's value

        // reduce gates over the 4 quarters
        gif = fadd2(gif, __shfl_xor_sync(FULL, gif, 1));
        gif = fadd2(gif, __shfl_xor_sync(FULL, gif, 2));
        ggo = fadd2(ggo, __shfl_xor_sync(FULL, ggo, 1));
        ggo = fadd2(ggo, __shfl_xor_sync(FULL, ggo, 2));

        // pointwise on q==0 — i,f,g,o already local, no gathers
        if (q == 0) {
            float gi, gf, gg, go;
            unpack2(gif, gi, gf);
            unpack2(ggo, gg, go);
            const float gamma = (t + 1 < NT)
                              ? __expf(-fmaxf(gamma_raw, 0.0f)) : 1.0f;
            const float ig = sigmoid_f(gi);
            const float fg = sigmoid_f(gf);
            const float tg = tanh_f(gg);
            const float og = sigmoid_f(go);
            const float cn = fg * c_reg + ig * tg;
            c_reg = cn;
            h_s[b][j] = og * tanh_f(cn) * gamma;   // pre-decayed
        }

        // m-dot for t+1 on q2/q3 (overlaps the pointwise tail)
        macc_if = bias_if; macc_go = bias_go;
        if (q >= 2) {
            const float4* mp = (const float4*)&m_s[nb][b][32 * (q - 2)];
            #pragma unroll
            for (int k = 0; k < 8; k++)
                gate_fma4(&wif[4 * k], &wgo[4 * k], mp[k], macc_if, macc_go);
        }
        __syncthreads();
    }

    // ---- output head: 4 scalars (2 batches x 2 classes) ----
    if (tid < 4) {
        const int cc = tid & 1, bsel = tid >> 1;
        float s = b_out[cc];
        #pragma unroll
        for (int jj = 0; jj < NH; jj++)
            s += W_out[cc * NH + jj] * h_s[bsel][jj];
        out[(size_t)(2 * blockIdx.x + bsel) * NC + cc] = s;
    }
}

extern "C" void kernel_launch(void* const* d_in, const int* in_sizes, int n_in,
                              void* d_out, int out_size)
{
    (void)in_sizes; (void)n_in; (void)out_size;
    const float* values  = (const float*)d_in[0];
    const float* masks   = (const float*)d_in[1];
    const float* deltas  = (const float*)d_in[2];
    const float* W_decay = (const float*)d_in[3];
    const float* b_decay = (const float*)d_in[4];
    const float* W_reg   = (const float*)d_in[5];
    const float* b_reg   = (const float*)d_in[6];
    const float* W_ih    = (const float*)d_in[7];
    const float* b_ih    = (const float*)d_in[8];
    const float* W_hh    = (const float*)d_in[9];
    const float* b_hh    = (const float*)d_in[10];
    const float* W_out   = (const float*)d_in[11];
    const float* b_out   = (const float*)d_in[12];
    float* out = (float*)d_out;

    rits_kernel<<<NB / 2, TPB>>>(values, masks, deltas,
                                 W_decay, b_decay, W_reg, b_reg,
                                 W_ih, b_ih, W_hh, b_hh,
                                 W_out, b_out, out);
}